// round 13
// baseline (speedup 1.0000x reference)
#include <cuda_runtime.h>
#include <cuda_fp16.h>
#include <cstdint>
#include <cstddef>

// Problem constants
#define B   64
#define P   2048
#define PD  16
#define N   32
#define D   32
#define ND  1024          // N*D
#define CH  128           // p's per chunk in pass kernel
#define NCH 16            // P / CH
#define SLOTS 32          // g_partial slots per b (max of 16 pass / 32 s0)
#define ROWB 2048         // bytes per p-row of pred (1024 halfs)

// per-warp ring in pass kernel
#define WBUF 3            // buffers per warp
#define WBUF_BYTES 4096   // 2 p-rows per buffer
#define WSTEPS 8          // 16 p's per warp / 2 per step
#define PASS_RING (8 * WBUF * WBUF_BYTES)          // 98304
#define PASS_SMEM (PASS_RING + 8 * WBUF * 8)       // + mbarriers

// pred kernel smem layout (bytes)
#define WST_BYTES (1024 * 48)
#define XST_BYTES (64 * 48)
#define CST_ROWB  144
#define CST_WARP  (16 * CST_ROWB)
#define PRED_SMEM (WST_BYTES + XST_BYTES + 8 * CST_WARP)

// Scratch (device globals: allocation-free per harness rules)
__device__ __half  g_pred[(size_t)B * P * ND];          // 268 MB (fp16, swizzled)
__device__ float   g_logits[(size_t)B * P * N];         // 16 MB
__device__ float   g_v[(size_t)B * ND];                 // 256 KB
__device__ float   g_partial[(size_t)B * SLOTS * ND];   // 8 MB

__device__ __forceinline__ uint32_t smem_u32(const void* p) {
    uint32_t a;
    asm("{ .reg .u64 t; cvta.to.shared.u64 t, %1; cvt.u32.u64 %0, t; }"
        : "=r"(a) : "l"(p));
    return a;
}

__device__ __forceinline__ void mbar_init(uint32_t mbar, uint32_t cnt) {
    asm volatile("mbarrier.init.shared.b64 [%0], %1;" :: "r"(mbar), "r"(cnt)
                 : "memory");
}
__device__ __forceinline__ void mbar_expect_tx(uint32_t mbar, uint32_t bytes) {
    asm volatile("mbarrier.arrive.expect_tx.shared.b64 _, [%0], %1;"
                 :: "r"(mbar), "r"(bytes) : "memory");
}
__device__ __forceinline__ void mbar_wait(uint32_t mbar, uint32_t parity) {
    asm volatile(
        "{\n\t"
        ".reg .pred P1;\n\t"
        "WAIT_LOOP_%=:\n\t"
        "mbarrier.try_wait.parity.acquire.cta.shared::cta.b64 P1, [%0], %1, 0x989680;\n\t"
        "@P1 bra.uni WAIT_DONE_%=;\n\t"
        "bra.uni WAIT_LOOP_%=;\n\t"
        "WAIT_DONE_%=:\n\t"
        "}"
        :: "r"(mbar), "r"(parity) : "memory");
}
__device__ __forceinline__ void bulk_g2s(uint32_t dst, const void* src,
                                         uint32_t bytes, uint32_t mbar) {
    asm volatile(
        "cp.async.bulk.shared::cluster.global.mbarrier::complete_tx::bytes "
        "[%0], [%1], %2, [%3];"
        :: "r"(dst), "l"(src), "r"(bytes), "r"(mbar) : "memory");
}

__device__ __forceinline__ void unpack8(const uint4& u, float* f) {
    const __half2* h = reinterpret_cast<const __half2*>(&u);
#pragma unroll
    for (int k = 0; k < 4; k++) {
        float2 t = __half22float2(h[k]);
        f[2 * k] = t.x; f[2 * k + 1] = t.y;
    }
}

// mma.sync helpers
__device__ __forceinline__ void ldsm_x4(uint32_t* r, uint32_t addr) {
    asm volatile("ldmatrix.sync.aligned.m8n8.x4.shared.b16 {%0,%1,%2,%3}, [%4];"
        : "=r"(r[0]), "=r"(r[1]), "=r"(r[2]), "=r"(r[3]) : "r"(addr));
}
__device__ __forceinline__ void ldsm_x2(uint32_t* r, uint32_t addr) {
    asm volatile("ldmatrix.sync.aligned.m8n8.x2.shared.b16 {%0,%1}, [%2];"
        : "=r"(r[0]), "=r"(r[1]) : "r"(addr));
}
__device__ __forceinline__ void stsm_x4(uint32_t addr, uint32_t r0, uint32_t r1,
                                        uint32_t r2, uint32_t r3) {
    asm volatile("stmatrix.sync.aligned.m8n8.x4.shared.b16 [%0], {%1,%2,%3,%4};"
        :: "r"(addr), "r"(r0), "r"(r1), "r"(r2), "r"(r3) : "memory");
}
__device__ __forceinline__ void mma16816(float* d, const uint32_t* a,
                                         const uint32_t* b) {
    asm volatile(
        "mma.sync.aligned.m16n8k16.row.col.f32.f16.f16.f32 "
        "{%0,%1,%2,%3}, {%4,%5,%6,%7}, {%8,%9}, {%10,%11,%12,%13};"
        : "=f"(d[0]), "=f"(d[1]), "=f"(d[2]), "=f"(d[3])
        : "r"(a[0]), "r"(a[1]), "r"(a[2]), "r"(a[3]),
          "r"(b[0]), "r"(b[1]),
          "f"(0.f), "f"(0.f), "f"(0.f), "f"(0.f));
}
__device__ __forceinline__ void mma16816_acc(float* d, const uint32_t* a,
                                             const uint32_t* b) {
    asm volatile(
        "mma.sync.aligned.m16n8k16.row.col.f32.f16.f16.f32 "
        "{%0,%1,%2,%3}, {%4,%5,%6,%7}, {%8,%9}, {%0,%1,%2,%3};"
        : "+f"(d[0]), "+f"(d[1]), "+f"(d[2]), "+f"(d[3])
        : "r"(a[0]), "r"(a[1]), "r"(a[2]), "r"(a[3]),
          "r"(b[0]), "r"(b[1]));
}

extern __shared__ char dsm[];

// ---------------------------------------------------------------------------
// Kernel S0: s0[b,e] = (1/32) * sum_{p,q} x[b,p,q] * w[p,e,q] directly from
// the fp32 inputs (fp16-quantized for HMMA, fp32 accumulation over all p).
// ---------------------------------------------------------------------------
__global__ __launch_bounds__(256) void s0_kernel(
    const float* __restrict__ x, const float* __restrict__ w) {
    __shared__ __align__(16) char wst_s[64 * 48];
    __shared__ __align__(16) char xst_s[64 * 48];

    const int pg = blockIdx.x;   // 0..31
    const int eg = blockIdx.y;   // 0..15
    const int t    = threadIdx.x;
    const int wp   = t >> 5;
    const int lane = t & 31;
    const int e0   = eg * 64;
    const int p0   = pg * 64;

    const uint32_t wst_addr = smem_u32(wst_s);
    const uint32_t xst_addr = smem_u32(xst_s);

    const int st_row = t >> 2, st_qb = t & 3;

    float c[4][4];
#pragma unroll
    for (int j = 0; j < 4; j++)
#pragma unroll
        for (int k = 0; k < 4; k++) c[j][k] = 0.f;

    float4 vw = reinterpret_cast<const float4*>(
        w + (size_t)p0 * (ND * PD) + (size_t)e0 * PD)[t];
    float4 vx = reinterpret_cast<const float4*>(
        x + ((size_t)st_row * P + p0) * PD)[st_qb];

    for (int i = 0; i < 64; i++) {
        {
            __half2 h0 = __floats2half2_rn(vw.x, vw.y);
            __half2 h1 = __floats2half2_rn(vw.z, vw.w);
            uint2 pk;
            pk.x = *reinterpret_cast<unsigned*>(&h0);
            pk.y = *reinterpret_cast<unsigned*>(&h1);
            *reinterpret_cast<uint2*>(wst_s + st_row * 48 + st_qb * 8) = pk;
            __half2 g0 = __floats2half2_rn(vx.x, vx.y);
            __half2 g1 = __floats2half2_rn(vx.z, vx.w);
            uint2 qk;
            qk.x = *reinterpret_cast<unsigned*>(&g0);
            qk.y = *reinterpret_cast<unsigned*>(&g1);
            *reinterpret_cast<uint2*>(xst_s + st_row * 48 + st_qb * 8) = qk;
        }
        if (i + 1 < 64) {
            const int p = p0 + i + 1;
            vw = reinterpret_cast<const float4*>(
                w + (size_t)p * (ND * PD) + (size_t)e0 * PD)[t];
            vx = reinterpret_cast<const float4*>(
                x + ((size_t)st_row * P + p) * PD)[st_qb];
        }
        __syncthreads();

        uint32_t afr[4];
        {
            const int mat = lane >> 3, r = lane & 7;
            ldsm_x4(afr, xst_addr +
                (16 * (wp >> 1) + (mat & 1) * 8 + r) * 48 + (mat >> 1) * 16);
        }
        uint32_t bfr[4][2];
#pragma unroll
        for (int j = 0; j < 4; j++) {
            const int nt = (wp & 1) * 4 + j;
            ldsm_x2(bfr[j], wst_addr +
                (nt * 8 + (lane & 7)) * 48 + ((lane >> 3) & 1) * 16);
        }
#pragma unroll
        for (int j = 0; j < 4; j++) mma16816_acc(c[j], afr, bfr[j]);

        __syncthreads();
    }

    const float S = 1.f / (float)N;
    const int m = (wp >> 1) * 16 + (lane >> 2);
#pragma unroll
    for (int j = 0; j < 4; j++) {
        const int col = ((wp & 1) * 4 + j) * 8 + (lane & 3) * 2;
        float* gp0 = g_partial + ((size_t)m * SLOTS + pg) * ND + e0 + col;
        float* gp1 = g_partial + ((size_t)(m + 8) * SLOTS + pg) * ND + e0 + col;
        *reinterpret_cast<float2*>(gp0) = make_float2(c[j][0] * S, c[j][1] * S);
        *reinterpret_cast<float2*>(gp1) = make_float2(c[j][2] * S, c[j][3] * S);
    }
}

// ---------------------------------------------------------------------------
// Kernel 1 (HMMA): pred[b,p,:] = X_p[b,q] * W_p[q,e], fp16 in / fp32 accum,
// stored fp16 with the 16B-chunk swizzle (slot = (k + ((n>>1)&3)) & 3).
// ---------------------------------------------------------------------------
__global__ __launch_bounds__(256, 2) void pred_kernel(
    const float* __restrict__ x, const float* __restrict__ w) {
    const int p    = blockIdx.x;
    const int t    = threadIdx.x;
    const int wp   = t >> 5;
    const int lane = t & 31;

    __half* wst = reinterpret_cast<__half*>(dsm);
    __half* xst = reinterpret_cast<__half*>(dsm + WST_BYTES);
    char*   cst = dsm + WST_BYTES + XST_BYTES;

    const uint32_t sbase    = smem_u32(dsm);
    const uint32_t wst_addr = sbase;
    const uint32_t xst_addr = sbase + WST_BYTES;
    const uint32_t cst_addr = sbase + WST_BYTES + XST_BYTES;

    {
        const float4* wrow = reinterpret_cast<const float4*>(
            w + (size_t)p * (ND * PD));
#pragma unroll
        for (int i = 0; i < 16; i++) {
            const int idx = t + 256 * i;
            const int e = idx >> 2, qb = idx & 3;
            float4 v = wrow[idx];
            __half2 h0 = __floats2half2_rn(v.x, v.y);
            __half2 h1 = __floats2half2_rn(v.z, v.w);
            uint2 pk;
            pk.x = *reinterpret_cast<unsigned*>(&h0);
            pk.y = *reinterpret_cast<unsigned*>(&h1);
            *reinterpret_cast<uint2*>(
                reinterpret_cast<char*>(wst) + e * 48 + qb * 8) = pk;
        }
    }
    {
        const int b = t >> 2, qb = t & 3;
        float4 v = reinterpret_cast<const float4*>(
            x + ((size_t)b * P + p) * PD)[qb];
        __half2 h0 = __floats2half2_rn(v.x, v.y);
        __half2 h1 = __floats2half2_rn(v.z, v.w);
        uint2 pk;
        pk.x = *reinterpret_cast<unsigned*>(&h0);
        pk.y = *reinterpret_cast<unsigned*>(&h1);
        *reinterpret_cast<uint2*>(
            reinterpret_cast<char*>(xst) + b * 48 + qb * 8) = pk;
    }
    __syncthreads();

    uint32_t afr[4][4];
#pragma unroll
    for (int mt = 0; mt < 4; mt++) {
        const int mat = lane >> 3, r = lane & 7;
        const uint32_t addr = xst_addr +
            (16 * mt + (mat & 1) * 8 + r) * 48 + (mat >> 1) * 16;
        ldsm_x4(afr[mt], addr);
    }

    const uint32_t cw = cst_addr + wp * CST_WARP;

#pragma unroll
    for (int eg = 0; eg < 2; eg++) {
        const int ebase = wp * 128 + eg * 64;

        uint32_t bfr[8][2];
#pragma unroll
        for (int j = 0; j < 8; j++) {
            const uint32_t addr = wst_addr +
                (ebase + 8 * j + (lane & 7)) * 48 + ((lane >> 3) & 1) * 16;
            ldsm_x2(bfr[j], addr);
        }

#pragma unroll
        for (int mt = 0; mt < 4; mt++) {
            float c[8][4];
#pragma unroll
            for (int j = 0; j < 8; j++) mma16816(c[j], afr[mt], bfr[j]);

            uint32_t h[8][2];
#pragma unroll
            for (int j = 0; j < 8; j++) {
                __half2 lo = __floats2half2_rn(c[j][0], c[j][1]);
                __half2 hi = __floats2half2_rn(c[j][2], c[j][3]);
                h[j][0] = *reinterpret_cast<unsigned*>(&lo);
                h[j][1] = *reinterpret_cast<unsigned*>(&hi);
            }

            const int r7 = lane & 7, m3 = lane >> 3;
            stsm_x4(cw + r7 * CST_ROWB + m3 * 16,
                    h[0][0], h[1][0], h[2][0], h[3][0]);
            stsm_x4(cw + r7 * CST_ROWB + (4 + m3) * 16,
                    h[4][0], h[5][0], h[6][0], h[7][0]);
            stsm_x4(cw + (r7 + 8) * CST_ROWB + m3 * 16,
                    h[0][1], h[1][1], h[2][1], h[3][1]);
            stsm_x4(cw + (r7 + 8) * CST_ROWB + (4 + m3) * 16,
                    h[4][1], h[5][1], h[6][1], h[7][1]);
            __syncwarp();

            const int bl = lane >> 1, cap = lane & 1;
            const int n  = wp * 4 + eg * 2 + cap;
            const int rot = (n >> 1) & 3;
            const int b   = 16 * mt + bl;
            char* gdst = reinterpret_cast<char*>(g_pred) +
                         ((size_t)b * P + p) * ROWB + n * 64;
            const char* csrc = cst + wp * CST_WARP + bl * CST_ROWB + cap * 64;
#pragma unroll
            for (int k = 0; k < 4; k++) {
                uint4 v = *reinterpret_cast<const uint4*>(csrc + k * 16);
                __stcs(reinterpret_cast<uint4*>(gdst + ((k + rot) & 3) * 16), v);
            }
            __syncwarp();
        }
    }
}

// ---------------------------------------------------------------------------
// Kernel 2: fused routing pass (iters 1..3), per-warp decoupled streaming.
// Block = (chunk, b); warp w owns a contiguous run of 16 p's and streams
// them through its PRIVATE ring of 3 x 4KB smem buffers (2 p-rows each) via
// cp.async.bulk with per-warp mbarriers. NO __syncthreads in the main loop:
// warps progress independently (softmax is warp-local, lane = n). Final
// cross-warp reduction is the only block barrier.
// ---------------------------------------------------------------------------
__global__ __launch_bounds__(256, 2) void pass_kernel(int iter) {
    const int chunk = blockIdx.x;
    const int b     = blockIdx.y;
    const int t     = threadIdx.x;
    const int w     = t >> 5;
    const int lane  = t & 31;
    const int rot   = (lane >> 1) & 3;

    const uint32_t smem_base = smem_u32(dsm);
    const uint32_t wbase = smem_base + w * (WBUF * WBUF_BYTES);
    const uint32_t mbase = smem_base + PASS_RING + w * (WBUF * 8);

    // this warp's 16 contiguous p's
    const char* gw = reinterpret_cast<const char*>(g_pred) +
                     ((size_t)b * P + (size_t)chunk * CH + (size_t)w * 16) * ROWB;

    if (lane == 0) {
#pragma unroll
        for (int k = 0; k < WBUF; k++) mbar_init(mbase + 8 * k, 1);
    }
    __syncwarp();
    if (lane == 0) {
#pragma unroll
        for (int k = 0; k < WBUF; k++) {
            mbar_expect_tx(mbase + 8 * k, WBUF_BYTES);
            bulk_g2s(wbase + k * WBUF_BYTES, gw + (size_t)k * WBUF_BYTES,
                     WBUF_BYTES, mbase + 8 * k);
        }
    }

    float v[32];
    {
        const float4* vp = reinterpret_cast<const float4*>(
            g_v + (size_t)b * ND + (size_t)lane * 32);
#pragma unroll
        for (int j = 0; j < 8; j++) {
            float4 q = vp[j];
            v[4 * j] = q.x; v[4 * j + 1] = q.y;
            v[4 * j + 2] = q.z; v[4 * j + 3] = q.w;
        }
    }

    float acc[32];
#pragma unroll
    for (int k = 0; k < 32; k++) acc[k] = 0.f;

    float* lgbase = g_logits +
        ((size_t)b * P + (size_t)chunk * CH + (size_t)w * 16) * N + lane;

#pragma unroll
    for (int s = 0; s < WSTEPS; s++) {
        const int buf = s % WBUF;
        const int par = (s / WBUF) & 1;
        const int pl0 = s * 2;

        // issue logit loads before the wait (latency hides under the copy)
        float lgv0 = 0.f, lgv1 = 0.f;
        if (iter >= 2) {
            lgv0 = lgbase[(size_t)pl0 * N];
            lgv1 = lgbase[(size_t)(pl0 + 1) * N];
        }

        mbar_wait(mbase + 8 * buf, par);
        const char* bufp = dsm + w * (WBUF * WBUF_BYTES) + buf * WBUF_BYTES;

#pragma unroll
        for (int j = 0; j < 2; j++) {
            const char* row = bufp + j * ROWB;

            uint4 q[4];
#pragma unroll
            for (int k = 0; k < 4; k++) {
                const int slot = (k + rot) & 3;
                q[k] = *reinterpret_cast<const uint4*>(row + lane * 64 + slot * 16);
            }

            float a0 = 0.f, a1 = 0.f, a2 = 0.f, a3 = 0.f;
            float fl[32];
#pragma unroll
            for (int c = 0; c < 4; c++) unpack8(q[c], fl + 8 * c);
#pragma unroll
            for (int k = 0; k < 8; k++) {
                a0 = fmaf(fl[k],      v[k],      a0);
                a1 = fmaf(fl[8 + k],  v[8 + k],  a1);
                a2 = fmaf(fl[16 + k], v[16 + k], a2);
                a3 = fmaf(fl[24 + k], v[24 + k], a3);
            }
            float lg = (a0 + a1) + (a2 + a3);
            if (iter >= 2) lg += (j == 0 ? lgv0 : lgv1);
            if (iter <= 2) lgbase[(size_t)(pl0 + j) * N] = lg;

            const float ex = __expf(lg);
            float se = ex;
#pragma unroll
            for (int o = 16; o > 0; o >>= 1)
                se += __shfl_xor_sync(0xffffffffu, se, o);
            const float c = __fdividef(ex, se);
#pragma unroll
            for (int k = 0; k < 32; k++) acc[k] = fmaf(c, fl[k], acc[k]);
        }

        __syncwarp();   // all lanes done reading this buffer
        if (lane == 0 && s + WBUF < WSTEPS) {
            mbar_expect_tx(mbase + 8 * buf, WBUF_BYTES);
            bulk_g2s(wbase + buf * WBUF_BYTES,
                     gw + (size_t)(s + WBUF) * WBUF_BYTES, WBUF_BYTES,
                     mbase + 8 * buf);
        }
    }

    // cross-warp reduction in smem (overlaps the now-idle ring buffers)
    __syncthreads();   // all warps done with their rings
    float* wsum = reinterpret_cast<float*>(dsm);
    float* ws = wsum + w * 1056 + lane;
#pragma unroll
    for (int d = 0; d < 32; d++) ws[d * 33] = acc[d];
    __syncthreads();

    float* op = g_partial + ((size_t)b * SLOTS + chunk) * ND;
#pragma unroll
    for (int jj = 0; jj < 4; jj++) {
        const int e = t + 256 * jj;
        const int n = e >> 5, d = e & 31;
        float sv = 0.f;
#pragma unroll
        for (int ww = 0; ww < 8; ww++) sv += wsum[ww * 1056 + d * 33 + n];
        op[e] = sv;
    }
}

// ---------------------------------------------------------------------------
// Kernel 3: reduce partials over nslots slots, squash over D, write v/out.
// ---------------------------------------------------------------------------
__global__ __launch_bounds__(256) void reduce_squash_kernel(
    float* __restrict__ out, int is_final, int nslots) {
    const int b = blockIdx.x;
    const int g = blockIdx.y;
    const int t = threadIdx.x;
    const int e = g * 256 + t;

    float s = 0.f;
    const float* pp = g_partial + (size_t)b * SLOTS * ND + e;
    for (int ch = 0; ch < nslots; ch++) s += pp[(size_t)ch * ND];

    float q = s * s;
#pragma unroll
    for (int o = 16; o > 0; o >>= 1)
        q += __shfl_xor_sync(0xffffffffu, q, o);
    const float EPS = 1e-7f;
    const float k = q / ((1.f + q) * sqrtf(q + EPS));

    float* dst = is_final ? (out + (size_t)b * ND) : (g_v + (size_t)b * ND);
    dst[e] = s * k;
}

// ---------------------------------------------------------------------------
extern "C" void kernel_launch(void* const* d_in, const int* in_sizes, int n_in,
                              void* d_out, int out_size) {
    const float* x = (const float*)d_in[0];
    const float* w = (const float*)d_in[1];
    if (n_in >= 2 && in_sizes[0] > in_sizes[1]) {
        const float* tmp = x; x = w; w = tmp;
    }
    float* out = (float*)d_out;

    cudaFuncSetAttribute(pass_kernel,
                         cudaFuncAttributeMaxDynamicSharedMemorySize, PASS_SMEM);
    cudaFuncSetAttribute(pred_kernel,
                         cudaFuncAttributeMaxDynamicSharedMemorySize, PRED_SMEM);

    // s0 directly from inputs (iter-0 pass replaced by a GEMM)
    s0_kernel<<<dim3(32, 16), 256>>>(x, w);
    reduce_squash_kernel<<<dim3(B, 4), 256>>>(out, 0, 32);
    pred_kernel<<<P, 256, PRED_SMEM>>>(x, w);
    for (int it = 1; it <= 3; it++) {
        pass_kernel<<<dim3(NCH, B), 256, PASS_SMEM>>>(it);
        reduce_squash_kernel<<<dim3(B, 4), 256>>>(out, it == 3 ? 1 : 0, 16);
    }
}

// round 14
// speedup vs baseline: 1.0499x; 1.0499x over previous
#include <cuda_runtime.h>
#include <cuda_fp16.h>
#include <cstdint>
#include <cstddef>

// Problem constants
#define B   64
#define P   2048
#define PD  16
#define N   32
#define D   32
#define ND  1024          // N*D
#define CH  128           // p's per chunk in pass kernel
#define NCH 16            // P / CH
#define SLOTS 32          // g_partial slots per b
#define ROWB 2048         // bytes per p-row of pred (1024 halfs)
#define STAGE_P 16
#define STAGE_BYTES (STAGE_P * ROWB)   // 32768
#define NBUF 3
#define NSTAGE 8          // CH / STAGE_P

// pred kernel smem layout (bytes)
#define WST_BYTES (1024 * 48)
#define XST_BYTES (64 * 48)
#define CST_ROWB  144
#define CST_WARP  (16 * CST_ROWB)
#define PRED_SMEM (WST_BYTES + XST_BYTES + 8 * CST_WARP)

// Scratch (device globals: allocation-free per harness rules)
__device__ __half  g_pred[(size_t)B * P * ND];          // 268 MB (fp16, swizzled)
__device__ float   g_logits[(size_t)B * P * N];         // 16 MB
__device__ float   g_v[(size_t)B * ND];                 // 256 KB
__device__ float   g_partial[(size_t)B * SLOTS * ND];   // 8 MB

__device__ __forceinline__ uint32_t smem_u32(const void* p) {
    uint32_t a;
    asm("{ .reg .u64 t; cvta.to.shared.u64 t, %1; cvt.u32.u64 %0, t; }"
        : "=r"(a) : "l"(p));
    return a;
}

__device__ __forceinline__ void mbar_init(uint32_t mbar, uint32_t cnt) {
    asm volatile("mbarrier.init.shared.b64 [%0], %1;" :: "r"(mbar), "r"(cnt)
                 : "memory");
}
__device__ __forceinline__ void mbar_expect_tx(uint32_t mbar, uint32_t bytes) {
    asm volatile("mbarrier.arrive.expect_tx.shared.b64 _, [%0], %1;"
                 :: "r"(mbar), "r"(bytes) : "memory");
}
__device__ __forceinline__ void mbar_wait(uint32_t mbar, uint32_t parity) {
    asm volatile(
        "{\n\t"
        ".reg .pred P1;\n\t"
        "WAIT_LOOP_%=:\n\t"
        "mbarrier.try_wait.parity.acquire.cta.shared::cta.b64 P1, [%0], %1, 0x989680;\n\t"
        "@P1 bra.uni WAIT_DONE_%=;\n\t"
        "bra.uni WAIT_LOOP_%=;\n\t"
        "WAIT_DONE_%=:\n\t"
        "}"
        :: "r"(mbar), "r"(parity) : "memory");
}
__device__ __forceinline__ void bulk_g2s(uint32_t dst, const void* src,
                                         uint32_t bytes, uint32_t mbar) {
    asm volatile(
        "cp.async.bulk.shared::cluster.global.mbarrier::complete_tx::bytes "
        "[%0], [%1], %2, [%3];"
        :: "r"(dst), "l"(src), "r"(bytes), "r"(mbar) : "memory");
}

__device__ __forceinline__ void unpack8(const uint4& u, float* f) {
    const __half2* h = reinterpret_cast<const __half2*>(&u);
#pragma unroll
    for (int k = 0; k < 4; k++) {
        float2 t = __half22float2(h[k]);
        f[2 * k] = t.x; f[2 * k + 1] = t.y;
    }
}

// mma.sync helpers
__device__ __forceinline__ void ldsm_x4(uint32_t* r, uint32_t addr) {
    asm volatile("ldmatrix.sync.aligned.m8n8.x4.shared.b16 {%0,%1,%2,%3}, [%4];"
        : "=r"(r[0]), "=r"(r[1]), "=r"(r[2]), "=r"(r[3]) : "r"(addr));
}
__device__ __forceinline__ void ldsm_x2(uint32_t* r, uint32_t addr) {
    asm volatile("ldmatrix.sync.aligned.m8n8.x2.shared.b16 {%0,%1}, [%2];"
        : "=r"(r[0]), "=r"(r[1]) : "r"(addr));
}
__device__ __forceinline__ void stsm_x4(uint32_t addr, uint32_t r0, uint32_t r1,
                                        uint32_t r2, uint32_t r3) {
    asm volatile("stmatrix.sync.aligned.m8n8.x4.shared.b16 [%0], {%1,%2,%3,%4};"
        :: "r"(addr), "r"(r0), "r"(r1), "r"(r2), "r"(r3) : "memory");
}
__device__ __forceinline__ void mma16816(float* d, const uint32_t* a,
                                         const uint32_t* b) {
    asm volatile(
        "mma.sync.aligned.m16n8k16.row.col.f32.f16.f16.f32 "
        "{%0,%1,%2,%3}, {%4,%5,%6,%7}, {%8,%9}, {%10,%11,%12,%13};"
        : "=f"(d[0]), "=f"(d[1]), "=f"(d[2]), "=f"(d[3])
        : "r"(a[0]), "r"(a[1]), "r"(a[2]), "r"(a[3]),
          "r"(b[0]), "r"(b[1]),
          "f"(0.f), "f"(0.f), "f"(0.f), "f"(0.f));
}
__device__ __forceinline__ void mma16816_acc(float* d, const uint32_t* a,
                                             const uint32_t* b) {
    asm volatile(
        "mma.sync.aligned.m16n8k16.row.col.f32.f16.f16.f32 "
        "{%0,%1,%2,%3}, {%4,%5,%6,%7}, {%8,%9}, {%0,%1,%2,%3};"
        : "+f"(d[0]), "+f"(d[1]), "+f"(d[2]), "+f"(d[3])
        : "r"(a[0]), "r"(a[1]), "r"(a[2]), "r"(a[3]),
          "r"(b[0]), "r"(b[1]));
}

extern __shared__ char dsm[];

// ---------------------------------------------------------------------------
// Kernel S0: s0[b,e] = (1/32) * sum_{p,q} x[b,p,q] * w[p,e,q] directly from
// the fp32 inputs (fp16-quantized for HMMA, fp32 accumulation over all p).
// ---------------------------------------------------------------------------
__global__ __launch_bounds__(256) void s0_kernel(
    const float* __restrict__ x, const float* __restrict__ w) {
    __shared__ __align__(16) char wst_s[64 * 48];
    __shared__ __align__(16) char xst_s[64 * 48];

    const int pg = blockIdx.x;   // 0..31
    const int eg = blockIdx.y;   // 0..15
    const int t    = threadIdx.x;
    const int wp   = t >> 5;
    const int lane = t & 31;
    const int e0   = eg * 64;
    const int p0   = pg * 64;

    const uint32_t wst_addr = smem_u32(wst_s);
    const uint32_t xst_addr = smem_u32(xst_s);

    const int st_row = t >> 2, st_qb = t & 3;

    float c[4][4];
#pragma unroll
    for (int j = 0; j < 4; j++)
#pragma unroll
        for (int k = 0; k < 4; k++) c[j][k] = 0.f;

    float4 vw = reinterpret_cast<const float4*>(
        w + (size_t)p0 * (ND * PD) + (size_t)e0 * PD)[t];
    float4 vx = reinterpret_cast<const float4*>(
        x + ((size_t)st_row * P + p0) * PD)[st_qb];

    for (int i = 0; i < 64; i++) {
        {
            __half2 h0 = __floats2half2_rn(vw.x, vw.y);
            __half2 h1 = __floats2half2_rn(vw.z, vw.w);
            uint2 pk;
            pk.x = *reinterpret_cast<unsigned*>(&h0);
            pk.y = *reinterpret_cast<unsigned*>(&h1);
            *reinterpret_cast<uint2*>(wst_s + st_row * 48 + st_qb * 8) = pk;
            __half2 g0 = __floats2half2_rn(vx.x, vx.y);
            __half2 g1 = __floats2half2_rn(vx.z, vx.w);
            uint2 qk;
            qk.x = *reinterpret_cast<unsigned*>(&g0);
            qk.y = *reinterpret_cast<unsigned*>(&g1);
            *reinterpret_cast<uint2*>(xst_s + st_row * 48 + st_qb * 8) = qk;
        }
        if (i + 1 < 64) {
            const int p = p0 + i + 1;
            vw = reinterpret_cast<const float4*>(
                w + (size_t)p * (ND * PD) + (size_t)e0 * PD)[t];
            vx = reinterpret_cast<const float4*>(
                x + ((size_t)st_row * P + p) * PD)[st_qb];
        }
        __syncthreads();

        uint32_t afr[4];
        {
            const int mat = lane >> 3, r = lane & 7;
            ldsm_x4(afr, xst_addr +
                (16 * (wp >> 1) + (mat & 1) * 8 + r) * 48 + (mat >> 1) * 16);
        }
        uint32_t bfr[4][2];
#pragma unroll
        for (int j = 0; j < 4; j++) {
            const int nt = (wp & 1) * 4 + j;
            ldsm_x2(bfr[j], wst_addr +
                (nt * 8 + (lane & 7)) * 48 + ((lane >> 3) & 1) * 16);
        }
#pragma unroll
        for (int j = 0; j < 4; j++) mma16816_acc(c[j], afr, bfr[j]);

        __syncthreads();
    }

    const float S = 1.f / (float)N;
    const int m = (wp >> 1) * 16 + (lane >> 2);
#pragma unroll
    for (int j = 0; j < 4; j++) {
        const int col = ((wp & 1) * 4 + j) * 8 + (lane & 3) * 2;
        float* gp0 = g_partial + ((size_t)m * SLOTS + pg) * ND + e0 + col;
        float* gp1 = g_partial + ((size_t)(m + 8) * SLOTS + pg) * ND + e0 + col;
        *reinterpret_cast<float2*>(gp0) = make_float2(c[j][0] * S, c[j][1] * S);
        *reinterpret_cast<float2*>(gp1) = make_float2(c[j][2] * S, c[j][3] * S);
    }
}

// ---------------------------------------------------------------------------
// Kernel 1 (HMMA): pred[b,p,:] = X_p[b,q] * W_p[q,e], fp16 in / fp32 accum,
// stored fp16 with the 16B-chunk swizzle (slot = (k + ((n>>1)&3)) & 3).
// ---------------------------------------------------------------------------
__global__ __launch_bounds__(256, 2) void pred_kernel(
    const float* __restrict__ x, const float* __restrict__ w) {
    const int p    = blockIdx.x;
    const int t    = threadIdx.x;
    const int wp   = t >> 5;
    const int lane = t & 31;

    __half* wst = reinterpret_cast<__half*>(dsm);
    __half* xst = reinterpret_cast<__half*>(dsm + WST_BYTES);
    char*   cst = dsm + WST_BYTES + XST_BYTES;

    const uint32_t sbase    = smem_u32(dsm);
    const uint32_t wst_addr = sbase;
    const uint32_t xst_addr = sbase + WST_BYTES;
    const uint32_t cst_addr = sbase + WST_BYTES + XST_BYTES;

    {
        const float4* wrow = reinterpret_cast<const float4*>(
            w + (size_t)p * (ND * PD));
#pragma unroll
        for (int i = 0; i < 16; i++) {
            const int idx = t + 256 * i;
            const int e = idx >> 2, qb = idx & 3;
            float4 v = wrow[idx];
            __half2 h0 = __floats2half2_rn(v.x, v.y);
            __half2 h1 = __floats2half2_rn(v.z, v.w);
            uint2 pk;
            pk.x = *reinterpret_cast<unsigned*>(&h0);
            pk.y = *reinterpret_cast<unsigned*>(&h1);
            *reinterpret_cast<uint2*>(
                reinterpret_cast<char*>(wst) + e * 48 + qb * 8) = pk;
        }
    }
    {
        const int b = t >> 2, qb = t & 3;
        float4 v = reinterpret_cast<const float4*>(
            x + ((size_t)b * P + p) * PD)[qb];
        __half2 h0 = __floats2half2_rn(v.x, v.y);
        __half2 h1 = __floats2half2_rn(v.z, v.w);
        uint2 pk;
        pk.x = *reinterpret_cast<unsigned*>(&h0);
        pk.y = *reinterpret_cast<unsigned*>(&h1);
        *reinterpret_cast<uint2*>(
            reinterpret_cast<char*>(xst) + b * 48 + qb * 8) = pk;
    }
    __syncthreads();

    uint32_t afr[4][4];
#pragma unroll
    for (int mt = 0; mt < 4; mt++) {
        const int mat = lane >> 3, r = lane & 7;
        const uint32_t addr = xst_addr +
            (16 * mt + (mat & 1) * 8 + r) * 48 + (mat >> 1) * 16;
        ldsm_x4(afr[mt], addr);
    }

    const uint32_t cw = cst_addr + wp * CST_WARP;

#pragma unroll
    for (int eg = 0; eg < 2; eg++) {
        const int ebase = wp * 128 + eg * 64;

        uint32_t bfr[8][2];
#pragma unroll
        for (int j = 0; j < 8; j++) {
            const uint32_t addr = wst_addr +
                (ebase + 8 * j + (lane & 7)) * 48 + ((lane >> 3) & 1) * 16;
            ldsm_x2(bfr[j], addr);
        }

#pragma unroll
        for (int mt = 0; mt < 4; mt++) {
            float c[8][4];
#pragma unroll
            for (int j = 0; j < 8; j++) mma16816(c[j], afr[mt], bfr[j]);

            uint32_t h[8][2];
#pragma unroll
            for (int j = 0; j < 8; j++) {
                __half2 lo = __floats2half2_rn(c[j][0], c[j][1]);
                __half2 hi = __floats2half2_rn(c[j][2], c[j][3]);
                h[j][0] = *reinterpret_cast<unsigned*>(&lo);
                h[j][1] = *reinterpret_cast<unsigned*>(&hi);
            }

            const int r7 = lane & 7, m3 = lane >> 3;
            stsm_x4(cw + r7 * CST_ROWB + m3 * 16,
                    h[0][0], h[1][0], h[2][0], h[3][0]);
            stsm_x4(cw + r7 * CST_ROWB + (4 + m3) * 16,
                    h[4][0], h[5][0], h[6][0], h[7][0]);
            stsm_x4(cw + (r7 + 8) * CST_ROWB + m3 * 16,
                    h[0][1], h[1][1], h[2][1], h[3][1]);
            stsm_x4(cw + (r7 + 8) * CST_ROWB + (4 + m3) * 16,
                    h[4][1], h[5][1], h[6][1], h[7][1]);
            __syncwarp();

            const int bl = lane >> 1, cap = lane & 1;
            const int n  = wp * 4 + eg * 2 + cap;
            const int rot = (n >> 1) & 3;
            const int b   = 16 * mt + bl;
            char* gdst = reinterpret_cast<char*>(g_pred) +
                         ((size_t)b * P + p) * ROWB + n * 64;
            const char* csrc = cst + wp * CST_WARP + bl * CST_ROWB + cap * 64;
#pragma unroll
            for (int k = 0; k < 4; k++) {
                uint4 v = *reinterpret_cast<const uint4*>(csrc + k * 16);
                __stcs(reinterpret_cast<uint4*>(gdst + ((k + rot) & 3) * 16), v);
            }
            __syncwarp();
        }
    }
}

// ---------------------------------------------------------------------------
// Kernel 2: fused routing pass (iters 1..3). Block = (chunk, b), 128 p's
// streamed through a 3x32KB smem ring via cp.async.bulk (R12 block-ring —
// the empirically best pass variant).
// ---------------------------------------------------------------------------
__global__ __launch_bounds__(256, 2) void pass_kernel(int iter) {
    const int chunk = blockIdx.x;
    const int b     = blockIdx.y;
    const int t     = threadIdx.x;
    const int w     = t >> 5;
    const int lane  = t & 31;
    const int rot   = (lane >> 1) & 3;

    const uint32_t smem_base = smem_u32(dsm);
    const uint32_t mbar_base = smem_base + NBUF * STAGE_BYTES;

    if (t == 0)
        for (int i = 0; i < NBUF; i++) mbar_init(mbar_base + 8 * i, 1);
    __syncthreads();

    const char* gsrc = reinterpret_cast<const char*>(g_pred) +
                       ((size_t)b * P + (size_t)chunk * CH) * ROWB;
    if (t == 0) {
#pragma unroll
        for (int s = 0; s < NBUF; s++) {
            mbar_expect_tx(mbar_base + 8 * s, STAGE_BYTES);
            bulk_g2s(smem_base + s * STAGE_BYTES,
                     gsrc + (size_t)s * STAGE_BYTES, STAGE_BYTES,
                     mbar_base + 8 * s);
        }
    }

    float v[32];
    {
        const float4* vp = reinterpret_cast<const float4*>(
            g_v + (size_t)b * ND + (size_t)lane * 32);
#pragma unroll
        for (int j = 0; j < 8; j++) {
            float4 q = vp[j];
            v[4 * j] = q.x; v[4 * j + 1] = q.y;
            v[4 * j + 2] = q.z; v[4 * j + 3] = q.w;
        }
    }

    float acc[32];
#pragma unroll
    for (int k = 0; k < 32; k++) acc[k] = 0.f;

    float* lgbase = g_logits + ((size_t)b * P + (size_t)chunk * CH) * N + lane;

#pragma unroll
    for (int s = 0; s < NSTAGE; s++) {
        const int buf = s % NBUF;
        const int par = (s / NBUF) & 1;
        const int pl0 = s * STAGE_P + w * 2;

        float lgv0 = 0.f, lgv1 = 0.f;
        if (iter >= 2) {
            lgv0 = lgbase[(size_t)pl0 * N];
            lgv1 = lgbase[(size_t)(pl0 + 1) * N];
        }

        mbar_wait(mbar_base + 8 * buf, par);
        const char* bufp = dsm + buf * STAGE_BYTES;

#pragma unroll
        for (int j = 0; j < 2; j++) {
            const int pl = pl0 + j;
            const char* row = bufp + (w * 2 + j) * ROWB;

            uint4 q[4];
#pragma unroll
            for (int k = 0; k < 4; k++) {
                const int slot = (k + rot) & 3;
                q[k] = *reinterpret_cast<const uint4*>(row + lane * 64 + slot * 16);
            }

            float a0 = 0.f, a1 = 0.f, a2 = 0.f, a3 = 0.f;
            float fl[32];
#pragma unroll
            for (int c = 0; c < 4; c++) unpack8(q[c], fl + 8 * c);
#pragma unroll
            for (int k = 0; k < 8; k++) {
                a0 = fmaf(fl[k],      v[k],      a0);
                a1 = fmaf(fl[8 + k],  v[8 + k],  a1);
                a2 = fmaf(fl[16 + k], v[16 + k], a2);
                a3 = fmaf(fl[24 + k], v[24 + k], a3);
            }
            float lg = (a0 + a1) + (a2 + a3);
            if (iter >= 2) lg += (j == 0 ? lgv0 : lgv1);
            if (iter <= 2) lgbase[(size_t)pl * N] = lg;

            const float ex = __expf(lg);
            float se = ex;
#pragma unroll
            for (int o = 16; o > 0; o >>= 1)
                se += __shfl_xor_sync(0xffffffffu, se, o);
            const float c = __fdividef(ex, se);
#pragma unroll
            for (int k = 0; k < 32; k++) acc[k] = fmaf(c, fl[k], acc[k]);
        }
        __syncthreads();
        if (t == 0 && s + NBUF < NSTAGE) {
            mbar_expect_tx(mbar_base + 8 * buf, STAGE_BYTES);
            bulk_g2s(smem_base + buf * STAGE_BYTES,
                     gsrc + (size_t)(s + NBUF) * STAGE_BYTES, STAGE_BYTES,
                     mbar_base + 8 * buf);
        }
    }

    // cross-warp reduction in smem (overlaps idle stage buffers)
    float* wsum = reinterpret_cast<float*>(dsm);
    float* ws = wsum + w * 1056 + lane;
#pragma unroll
    for (int d = 0; d < 32; d++) ws[d * 33] = acc[d];
    __syncthreads();

    float* op = g_partial + ((size_t)b * SLOTS + chunk) * ND;
#pragma unroll
    for (int jj = 0; jj < 4; jj++) {
        const int e = t + 256 * jj;
        const int n = e >> 5, d = e & 31;
        float sv = 0.f;
#pragma unroll
        for (int ww = 0; ww < 8; ww++) sv += wsum[ww * 1056 + d * 33 + n];
        op[e] = sv;
    }
}

// ---------------------------------------------------------------------------
// Kernel 3: reduce partials over nslots slots, squash over D, write v/out.
// ---------------------------------------------------------------------------
__global__ __launch_bounds__(256) void reduce_squash_kernel(
    float* __restrict__ out, int is_final, int nslots) {
    const int b = blockIdx.x;
    const int g = blockIdx.y;
    const int t = threadIdx.x;
    const int e = g * 256 + t;

    float s = 0.f;
    const float* pp = g_partial + (size_t)b * SLOTS * ND + e;
    for (int ch = 0; ch < nslots; ch++) s += pp[(size_t)ch * ND];

    float q = s * s;
#pragma unroll
    for (int o = 16; o > 0; o >>= 1)
        q += __shfl_xor_sync(0xffffffffu, q, o);
    const float EPS = 1e-7f;
    const float k = q / ((1.f + q) * sqrtf(q + EPS));

    float* dst = is_final ? (out + (size_t)b * ND) : (g_v + (size_t)b * ND);
    dst[e] = s * k;
}

// ---------------------------------------------------------------------------
extern "C" void kernel_launch(void* const* d_in, const int* in_sizes, int n_in,
                              void* d_out, int out_size) {
    const float* x = (const float*)d_in[0];
    const float* w = (const float*)d_in[1];
    if (n_in >= 2 && in_sizes[0] > in_sizes[1]) {
        const float* tmp = x; x = w; w = tmp;
    }
    float* out = (float*)d_out;

    // one-time (first call is the uncaptured correctness run)
    static cudaStream_t s2 = nullptr;
    static cudaEvent_t evFork = nullptr, evJoin = nullptr;
    static bool attrs_set = false;
    if (!attrs_set) {
        attrs_set = true;
        cudaStreamCreateWithFlags(&s2, cudaStreamNonBlocking);
        cudaEventCreateWithFlags(&evFork, cudaEventDisableTiming);
        cudaEventCreateWithFlags(&evJoin, cudaEventDisableTiming);
        cudaFuncSetAttribute(pass_kernel,
            cudaFuncAttributeMaxDynamicSharedMemorySize,
            NBUF * STAGE_BYTES + 8 * NBUF);
        cudaFuncSetAttribute(pred_kernel,
            cudaFuncAttributeMaxDynamicSharedMemorySize, PRED_SMEM);
    }
    const int dyn_pass = NBUF * STAGE_BYTES + 8 * NBUF;

    // fork: side stream runs s0 + reduce0 while main stream runs pred
    cudaEventRecord(evFork, 0);
    cudaStreamWaitEvent(s2, evFork, 0);
    s0_kernel<<<dim3(32, 16), 256, 0, s2>>>(x, w);
    reduce_squash_kernel<<<dim3(B, 4), 256, 0, s2>>>(out, 0, 32);
    cudaEventRecord(evJoin, s2);

    pred_kernel<<<P, 256, PRED_SMEM>>>(x, w);

    // join: pass1 needs both g_pred (main) and g_v (side)
    cudaStreamWaitEvent(0, evJoin, 0);

    for (int it = 1; it <= 3; it++) {
        pass_kernel<<<dim3(NCH, B), 256, dyn_pass>>>(it);
        reduce_squash_kernel<<<dim3(B, 4), 256>>>(out, it == 3 ? 1 : 0, 16);
    }
}